// round 16
// baseline (speedup 1.0000x reference)
#include <cuda_runtime.h>
#include <cuda_bf16.h>
#include <cstdint>

// ---------------------------------------------------------------------------
// loss2, 2 launches:
//   1) normalize -> bf16 (8 threads/row) + zero g_rowsum
//   2) ONE grid of exactly NJ + NPAIR CTAs (sized to the 2-CTA/SM residency
//      capacity so every CTA is wave-1 co-resident):
//      - NJ rowsum CTAs (R10-proven mainloop): bf16 mma.sync over
//        upper-triangle tile chunks (symmetry), packed-f32x2 degree-6 exp
//        epilogue -> row + (off-diag) col sums via fp32 atomicAdd; signal
//        g_done at exit.
//      - NPAIR pairs CTAs: stage block cosines + exps into their (otherwise
//        idle) smem WHILE the GEMM runs, nanosleep-spin on g_done, then only
//        negA + logs remain; counter-fused finalize writes out.
// ---------------------------------------------------------------------------

#define C_DIM 128
#define BLK 5
#define MAX_T 4096
#define TM 128
#define NTHR 256
#define NSM 148
#define MAXBPC 64

__device__ __align__(16) __nv_bfloat16 g_xbf[MAX_T * C_DIM];  // zero-init: rows>=T are 0
__device__ float g_rowsum[MAX_T];
__device__ float g_pairpart[64];
__device__ int   g_done;               // rowsum CTAs arrived; reset by last pairs CTA
__device__ int   g_cnt;                // pairs CTAs arrived; self-resetting

// smem: A 32KB @0, B tiles @32768 and @65536  -> 96KB per CTA (2 CTAs/SM)
#define OFF_A  0
#define OFF_B0 32768
#define OFF_B1 65536
#define SMEM_DYN 98304

// ---------------- helpers ----------------
__device__ __forceinline__ uint32_t smem_u32(const void* p) {
    uint32_t a;
    asm("{ .reg .u64 t; cvta.to.shared.u64 t, %1; cvt.u32.u64 %0, t; }" : "=r"(a) : "l"(p));
    return a;
}

__device__ __forceinline__ void cp_async16(uint32_t dst, const void* src) {
    asm volatile("cp.async.cg.shared.global [%0], [%1], 16;"
                 :: "r"(dst), "l"(__cvta_generic_to_global(src)));
}
#define CP_COMMIT()  asm volatile("cp.async.commit_group;" ::: "memory")
#define CP_WAIT(n)   asm volatile("cp.async.wait_group %0;" :: "n"(n) : "memory")

__device__ __forceinline__ void ldmatrix_x4(uint32_t* r, uint32_t addr) {
    asm volatile("ldmatrix.sync.aligned.m8n8.x4.shared.b16 {%0,%1,%2,%3}, [%4];"
                 : "=r"(r[0]), "=r"(r[1]), "=r"(r[2]), "=r"(r[3]) : "r"(addr));
}

__device__ __forceinline__ void mma_bf16(float* c, const uint32_t* a, const uint32_t* b) {
    asm volatile(
        "mma.sync.aligned.m16n8k16.row.col.f32.bf16.bf16.f32 "
        "{%0,%1,%2,%3}, {%4,%5,%6,%7}, {%8,%9}, {%0,%1,%2,%3};"
        : "+f"(c[0]), "+f"(c[1]), "+f"(c[2]), "+f"(c[3])
        : "r"(a[0]), "r"(a[1]), "r"(a[2]), "r"(a[3]), "r"(b[0]), "r"(b[1]));
}

// ---------------- fp32x2 packed math ----------------
__device__ __forceinline__ unsigned long long pk2(float lo, float hi) {
    unsigned long long r;
    asm("mov.b64 %0, {%1, %2};" : "=l"(r) : "f"(lo), "f"(hi));
    return r;
}
__device__ __forceinline__ float2 up2(unsigned long long v) {
    float2 r;
    asm("mov.b64 {%0, %1}, %2;" : "=f"(r.x), "=f"(r.y) : "l"(v));
    return r;
}
__device__ __forceinline__ unsigned long long fma2(unsigned long long a,
                                                   unsigned long long b,
                                                   unsigned long long c) {
    unsigned long long d;
    asm("fma.rn.f32x2 %0, %1, %2, %3;" : "=l"(d) : "l"(a), "l"(b), "l"(c));
    return d;
}
__device__ __forceinline__ unsigned long long add2(unsigned long long a,
                                                   unsigned long long b) {
    unsigned long long d;
    asm("add.rn.f32x2 %0, %1, %2;" : "=l"(d) : "l"(a), "l"(b));
    return d;
}
// exp(c) for |c| <= ~1.05, degree-6 Taylor; exp_pk(0) == 1.0 exactly.
__device__ __forceinline__ unsigned long long exp_pk(unsigned long long c) {
    unsigned long long p = pk2(1.3888889e-3f, 1.3888889e-3f);   // 1/6!
    p = fma2(p, c, pk2(8.3333333e-3f, 8.3333333e-3f));          // 1/5!
    p = fma2(p, c, pk2(4.1666667e-2f, 4.1666667e-2f));          // 1/4!
    p = fma2(p, c, pk2(1.6666667e-1f, 1.6666667e-1f));          // 1/3!
    p = fma2(p, c, pk2(0.5f, 0.5f));
    p = fma2(p, c, pk2(1.0f, 1.0f));
    p = fma2(p, c, pk2(1.0f, 1.0f));
    return p;
}

// tile smem layout: row-major 128 rows x 256B, 16B chunks XOR-swizzled by (row&7)
__device__ __forceinline__ void copy_tile_async(uint32_t dstb, int grow0, int tid) {
    #pragma unroll
    for (int l = 0; l < 8; l++) {
        int idx = tid + l * NTHR;              // 0..2047
        int row = idx >> 4;
        int ch  = idx & 15;
        cp_async16(dstb + row * 256 + ((ch ^ (row & 7)) << 4),
                   &g_xbf[(grow0 + row) * C_DIM + ch * 8]);
    }
}

// flat chunk index -> (it, jt0, njt): panel it, chunk q covers jt = it+2q, +1
__device__ __forceinline__ void job_decode(int f, int ntM, int& it, int& jt0, int& njt) {
    int i = 0;
    for (;;) {
        int pairs = (ntM - i + 1) >> 1;
        if (f < pairs) { it = i; jt0 = i + f * 2; njt = min(2, ntM - jt0); return; }
        f -= pairs; ++i;
    }
}

// ---------------- kernels ----------------
__global__ __launch_bounds__(512) void normalize_kernel(const float* __restrict__ x, int T) {
    int tid = blockIdx.x * 512 + threadIdx.x;
    if (tid < MAX_T) g_rowsum[tid] = 0.f;      // per-replay reset
    int row = tid >> 3;
    int sub = tid & 7;                         // 8 threads per row, 16 floats each
    if (row < T) {
        const float4* px = (const float4*)&x[row * C_DIM + sub * 16];
        float4 v0 = px[0], v1 = px[1], v2 = px[2], v3 = px[3];
        float s = v0.x*v0.x + v0.y*v0.y + v0.z*v0.z + v0.w*v0.w
                + v1.x*v1.x + v1.y*v1.y + v1.z*v1.z + v1.w*v1.w
                + v2.x*v2.x + v2.y*v2.y + v2.z*v2.z + v2.w*v2.w
                + v3.x*v3.x + v3.y*v3.y + v3.z*v3.z + v3.w*v3.w;
        #pragma unroll
        for (int o = 1; o < 8; o <<= 1) s += __shfl_xor_sync(0xffffffffu, s, o);
        float inv = 1.0f / fmaxf(sqrtf(s), 1e-8f);
        __nv_bfloat16* dst = &g_xbf[row * C_DIM + sub * 16];
        float4 vv[4] = {v0, v1, v2, v3};
        #pragma unroll
        for (int q = 0; q < 4; q++) {
            __nv_bfloat162 o0 = __floats2bfloat162_rn(vv[q].x * inv, vv[q].y * inv);
            __nv_bfloat162 o1 = __floats2bfloat162_rn(vv[q].z * inv, vv[q].w * inv);
            uint2 pk;
            pk.x = *(uint32_t*)&o0;
            pk.y = *(uint32_t*)&o1;
            *(uint2*)(dst + q * 4) = pk;
        }
    }
}

__global__ void __launch_bounds__(NTHR, 2) rowsum_fused(
    int T, int ntM, int NJ, float rscale, int Bnum, int npair, int bpc,
    const int* __restrict__ kuai2, float* __restrict__ out)
{
    extern __shared__ char smem[];
    const int tid  = threadIdx.x;
    const int wid  = tid >> 5;                 // 0..7
    const int lane = tid & 31;

    if ((int)blockIdx.x < NJ) {
        // ==================== rowsum path (R10-proven) ====================
        const uint32_t sb = smem_u32(smem);
        int it, jt0, njt;
        job_decode(blockIdx.x, ntM, it, jt0, njt);
        const int i0 = it * TM;

        copy_tile_async(sb + OFF_A, i0, tid);
        copy_tile_async(sb + OFF_B0, jt0 * TM, tid);
        CP_COMMIT();
        if (njt == 2) {
            copy_tile_async(sb + OFF_B1, (jt0 + 1) * TM, tid);
            CP_COMMIT();
        }

        const int mq = wid >> 1;               // M quarter: 32 rows
        const int nh = wid & 1;                // N half: 64 cols of 128
        const int mrow = mq * 32;
        const int jloc = nh * 64;
        const int s7   = lane & 7;

        const int ro_a = (lane & 7) + ((lane >> 3) & 1) * 8;
        const int cg_a = (lane >> 4);
        const int ro_b = (lane & 7) + ((lane >> 4) & 1) * 8;
        const int cg_b = (lane >> 3) & 1;

        uint32_t a_addr[2];
        #pragma unroll
        for (int mi = 0; mi < 2; mi++)
            a_addr[mi] = sb + OFF_A + (mrow + mi * 16 + ro_a) * 256;

        for (int s = 0; s < njt; s++) {
            if (s == 0) { if (njt == 2) { CP_WAIT(1); } else { CP_WAIT(0); } }
            else        { CP_WAIT(0); }
            __syncthreads();

            const int jt  = jt0 + s;
            const int gj0 = jt * TM + jloc;
            const uint32_t bt = sb + (s ? OFF_B1 : OFF_B0);
            uint32_t b_addr[4];
            #pragma unroll
            for (int p = 0; p < 4; p++)
                b_addr[p] = bt + (jloc + p * 16 + ro_b) * 256;

            float c[2][8][4];
            #pragma unroll
            for (int mi = 0; mi < 2; mi++)
                #pragma unroll
                for (int ni = 0; ni < 8; ni++)
                    #pragma unroll
                    for (int q = 0; q < 4; q++) c[mi][ni][q] = 0.f;

            #pragma unroll
            for (int ks = 0; ks < 8; ks++) {
                const uint32_t chA = (uint32_t)(((ks * 2 + cg_a) ^ s7) << 4);
                const uint32_t chB = (uint32_t)(((ks * 2 + cg_b) ^ s7) << 4);
                uint32_t a[2][4], b[4][4];
                #pragma unroll
                for (int mi = 0; mi < 2; mi++) ldmatrix_x4(a[mi], a_addr[mi] + chA);
                #pragma unroll
                for (int p = 0; p < 4; p++)    ldmatrix_x4(b[p], b_addr[p] + chB);
                #pragma unroll
                for (int mi = 0; mi < 2; mi++)
                    #pragma unroll
                    for (int ni = 0; ni < 8; ni++)
                        mma_bf16(c[mi][ni], a[mi], &b[ni >> 1][(ni & 1) * 2]);
            }

            // ---- epilogue: exp once; row sums + (off-diag) col sums ----
            unsigned long long racc[4] = {0ull, 0ull, 0ull, 0ull};
            unsigned long long cacc[8] = {0ull,0ull,0ull,0ull,0ull,0ull,0ull,0ull};
            #pragma unroll
            for (int mi = 0; mi < 2; mi++)
                #pragma unroll
                for (int ni = 0; ni < 8; ni++) {
                    unsigned long long e01 = exp_pk(pk2(c[mi][ni][0], c[mi][ni][1]));
                    unsigned long long e23 = exp_pk(pk2(c[mi][ni][2], c[mi][ni][3]));
                    racc[mi * 2]     = add2(racc[mi * 2], e01);
                    racc[mi * 2 + 1] = add2(racc[mi * 2 + 1], e23);
                    cacc[ni]         = add2(cacc[ni], add2(e01, e23));
                }

            int padc = 0;
            if (gj0 + 64 > T) {
                #pragma unroll
                for (int ni = 0; ni < 8; ni++) {
                    int col = gj0 + ni * 8 + 2 * (lane & 3);
                    padc += (col >= T) + (col + 1 >= T);
                }
            }
            float rrow[4];
            #pragma unroll
            for (int q = 0; q < 4; q++) {
                float2 u = up2(racc[q]);
                rrow[q] = (u.x + u.y) - (float)padc;
                rrow[q] += __shfl_xor_sync(0xffffffffu, rrow[q], 1);
                rrow[q] += __shfl_xor_sync(0xffffffffu, rrow[q], 2);
            }
            if ((lane & 3) == 0) {
                int rbase = i0 + mrow + (lane >> 2);
                #pragma unroll
                for (int mi = 0; mi < 2; mi++)
                    #pragma unroll
                    for (int h = 0; h < 2; h++) {
                        int row = rbase + mi * 16 + h * 8;
                        if (row < T) atomicAdd(&g_rowsum[row], rrow[mi * 2 + h]);
                    }
            }

            if (jt != it) {
                float padr = (float)min(32, max(0, i0 + mrow + 32 - T));
                #pragma unroll
                for (int ni = 0; ni < 8; ni++) {
                    float2 u = up2(cacc[ni]);
                    #pragma unroll
                    for (int o = 4; o <= 16; o <<= 1) {
                        u.x += __shfl_xor_sync(0xffffffffu, u.x, o);
                        u.y += __shfl_xor_sync(0xffffffffu, u.y, o);
                    }
                    if (lane < 4) {
                        int col = gj0 + ni * 8 + 2 * lane;
                        if (col < T)     atomicAdd(&g_rowsum[col],     u.x - padr);
                        if (col + 1 < T) atomicAdd(&g_rowsum[col + 1], u.y - padr);
                    }
                }
            }
        }

        __syncthreads();
        __threadfence();
        if (tid == 0) atomicAdd(&g_done, 1);
        return;
    }

    // ==================== pairs path (overlap CTAs) ====================
    const int pb   = (int)blockIdx.x - NJ;
    const int bst  = pb * bpc;
    const int bend = min(Bnum, bst + bpc);

    // smem staging: cmS[local][25], esS[local][25]
    float* cmS = (float*)smem;                 // bpc * 25 floats
    float* esS = cmS + MAXBPC * 25;            // bpc * 25 floats

    // Phase 1 (during GEMM): cosines + exps for my blocks
    for (int blk = bst + wid; blk < bend; blk += 8) {
        const int loc = blk - bst;
        float4 u[BLK];
        #pragma unroll
        for (int m = 0; m < BLK; m++) {
            const __nv_bfloat162* p =
                (const __nv_bfloat162*)&g_xbf[(blk * BLK + m) * C_DIM + lane * 4];
            float2 lo = __bfloat1622float2(p[0]);
            float2 hi = __bfloat1622float2(p[1]);
            u[m] = make_float4(lo.x, lo.y, hi.x, hi.y);
        }
        #pragma unroll
        for (int i = 0; i < BLK; i++)
            #pragma unroll
            for (int j = i; j < BLK; j++) {
                float s = u[i].x * u[j].x + u[i].y * u[j].y
                        + u[i].z * u[j].z + u[i].w * u[j].w;
                #pragma unroll
                for (int o = 16; o > 0; o >>= 1) s += __shfl_xor_sync(0xffffffffu, s, o);
                if (lane == 0) {
                    float e = expf(s);
                    cmS[loc * 25 + i * BLK + j] = s;
                    cmS[loc * 25 + j * BLK + i] = s;
                    esS[loc * 25 + i * BLK + j] = e;
                    esS[loc * 25 + j * BLK + i] = e;
                }
            }
    }
    __syncthreads();

    // wait for all rowsum CTAs
    if (tid == 0) {
        while (atomicAdd(&g_done, 0) < NJ) { __nanosleep(256); }
    }
    __syncthreads();
    __threadfence();

    // Phase 2: negA + logs only
    float warp_term = 0.f;
    for (int blk = bst + wid; blk < bend; blk += 8) {
        const int loc = blk - bst;
        float term = 0.f;
        if (lane < BLK) {
            int i = lane;
            float bsum = 0.f;
            #pragma unroll
            for (int m = 0; m < BLK; m++) bsum += esS[loc * 25 + i * BLK + m];
            float rs = __ldcg(&g_rowsum[blk * BLK + i]);
            float negA = rscale * (rs - bsum);
            #pragma unroll
            for (int m = 0; m < BLK; m++)
                if (m != i)
                    term += logf(esS[loc * 25 + i * BLK + m] + negA)
                          - cmS[loc * 25 + i * BLK + m];
        }
        #pragma unroll
        for (int o = 16; o > 0; o >>= 1) term += __shfl_xor_sync(0xffffffffu, term, o);
        warp_term += term;
    }

    __shared__ float ws[8];
    __shared__ int s_fin;
    if (lane == 0) ws[wid] = warp_term;
    __syncthreads();
    if (tid == 0) {
        float s = 0.f;
        #pragma unroll
        for (int k = 0; k < 8; k++) s += ws[k];
        g_pairpart[pb] = s;
        __threadfence();
        int o = atomicAdd(&g_cnt, 1);
        s_fin = (o == npair - 1);
        if (s_fin) { g_cnt = 0; g_done = 0; }  // reset for next replay
    }
    __syncthreads();
    if (s_fin && tid < 32) {
        __threadfence();
        double s = 0.0;
        for (int i = tid; i < npair; i += 32) s += (double)g_pairpart[i];
        #pragma unroll
        for (int o = 16; o > 0; o >>= 1) s += __shfl_xor_sync(0xffffffffu, s, o);
        if (tid == 0) {
            int k2 = *kuai2;
            out[0] = (float)(s / ((double)Bnum * (double)k2 * (double)(k2 - 1)));
        }
    }
}

// ---------------- launch ----------------
extern "C" void kernel_launch(void* const* d_in, const int* in_sizes, int n_in,
                              void* d_out, int out_size) {
    const float* x     = (const float*)d_in[0];
    const int*   kuai2 = (const int*)d_in[1];

    int T = in_sizes[0] / C_DIM;
    int B = T / BLK;
    float r = (float)(2 * B - 2) / (float)(T - BLK);
    int ntM = (T + TM - 1) / TM;

    int NJ = 0;
    for (int i = 0; i < ntM; i++) NJ += (ntM - i + 1) >> 1;   // rowsum chunk count

    // pairs CTAs fill the REMAINING wave-1 slots (2 CTAs/SM capacity)
    int slots = 2 * NSM;
    int npair = slots - NJ;
    if (npair < 1) npair = 8;                                  // fallback (still correct)
    int bpc = (B + npair - 1) / npair;
    if (bpc > MAXBPC) { bpc = MAXBPC; npair = (B + bpc - 1) / bpc; }
    int nthr_norm = ((T * 8 > MAX_T) ? T * 8 : MAX_T);

    cudaFuncSetAttribute(rowsum_fused, cudaFuncAttributeMaxDynamicSharedMemorySize, SMEM_DYN);

    normalize_kernel<<<(nthr_norm + 511) / 512, 512>>>(x, T);
    rowsum_fused<<<NJ + npair, NTHR, SMEM_DYN>>>(
        T, ntM, NJ, r, B, npair, bpc, kuai2, (float*)d_out);
}